// round 7
// baseline (speedup 1.0000x reference)
#include <cuda_runtime.h>

#define NPIX 786432
#define KER 9
#define CIN 16
#define COUT 16
#define TPB 128
#define PPT 4          // pixels per thread

typedef unsigned long long u64;

__device__ __forceinline__ u64 pack2(float lo, float hi) {
    u64 r; asm("mov.b64 %0, {%1, %2};" : "=l"(r) : "f"(lo), "f"(hi)); return r;
}
__device__ __forceinline__ void unpack2(u64 v, float& lo, float& hi) {
    asm("mov.b64 {%0, %1}, %2;" : "=f"(lo), "=f"(hi) : "l"(v));
}
__device__ __forceinline__ void fma2(u64& d, u64 a, u64 b) {
    asm("fma.rn.f32x2 %0, %1, %2, %0;" : "+l"(d) : "l"(a), "l"(b));
}
__device__ __forceinline__ void add2(u64& d, u64 a) {
    asm("add.rn.f32x2 %0, %0, %1;" : "+l"(d) : "l"(a));
}

__global__ __launch_bounds__(TPB) void healpix_conv_kernel(
    const float* __restrict__ x,      // (2, NPIX, CIN)
    const int*   __restrict__ nb,     // (NPIX, KER)
    const float* __restrict__ w,      // (COUT, KER, CIN)
    const float* __restrict__ bias,   // (COUT,)
    float*       __restrict__ y)      // (2, NPIX, COUT)
{
    // w duplicated into (w,w) f32x2 pairs, layout [k][o][c]: the 4 lanes of a
    // pixel-group read contiguous c -> conflict-free LDS.128 multi-broadcast.
    __shared__ u64 wdup[KER * COUT * CIN];

    const int tid = threadIdx.x;
    for (int i = tid; i < KER * COUT * CIN; i += TPB) {
        const int c = i & 15;
        const int o = (i >> 4) & 15;
        const int k = i >> 8;
        const float wv = w[(o * KER + k) * CIN + c];
        wdup[i] = pack2(wv, wv);
    }
    __syncthreads();

    const int lane = tid & 31;
    const int warp = tid >> 5;
    const int q = lane & 3;        // channel-quarter owned by this lane
    const int g = lane >> 2;       // pixel group (0..7)
    const int wb = (blockIdx.x * (TPB / 32) + warp) * 32;   // 32 pixels / warp

    u64 acc[PPT][COUT];
    #pragma unroll
    for (int p = 0; p < PPT; p++)
        #pragma unroll
        for (int o = 0; o < COUT; o++) acc[p][o] = 0ULL;

    // quarter-row base pointers for each batch
    const float* xq0 = x + q * 4;
    const float* xq1 = x + (size_t)NPIX * CIN + q * 4;

    const int* nbp[PPT];
    #pragma unroll
    for (int p = 0; p < PPT; p++)
        nbp[p] = nb + (size_t)(wb + p * 8 + g) * KER;

    // software pipeline depth 1 on the neighbour indices: the idx loads for
    // iteration k+1 issue before the FMA block of iteration k, so the
    // idx->gather serial chain is never exposed.
    int idv[PPT];
    #pragma unroll
    for (int p = 0; p < PPT; p++) idv[p] = nbp[p][0];

    #pragma unroll 1
    for (int k = 0; k < KER; k++) {
        u64 xp[PPT][4];
        #pragma unroll
        for (int p = 0; p < PPT; p++) {
            const int id = idv[p];
            const int safe = (id < NPIX) ? id : 0;
            const float4 a = *(const float4*)(xq0 + (size_t)safe * CIN);
            const float4 b = *(const float4*)(xq1 + (size_t)safe * CIN);
            const bool valid = (id < NPIX);
            xp[p][0] = valid ? pack2(a.x, b.x) : 0ULL;
            xp[p][1] = valid ? pack2(a.y, b.y) : 0ULL;
            xp[p][2] = valid ? pack2(a.z, b.z) : 0ULL;
            xp[p][3] = valid ? pack2(a.w, b.w) : 0ULL;
        }

        // prefetch next iteration's indices
        if (k + 1 < KER) {
            #pragma unroll
            for (int p = 0; p < PPT; p++) idv[p] = nbp[p][k + 1];
        }

        const u64* wk = wdup + k * COUT * CIN + q * 4;
        #pragma unroll
        for (int o = 0; o < COUT; o++) {
            const ulonglong2 wA = *(const ulonglong2*)(wk + o * CIN);
            const ulonglong2 wB = *(const ulonglong2*)(wk + o * CIN + 2);
            #pragma unroll
            for (int p = 0; p < PPT; p++) {
                fma2(acc[p][o], xp[p][0], wA.x);
                fma2(acc[p][o], xp[p][1], wA.y);
                fma2(acc[p][o], xp[p][2], wB.x);
                fma2(acc[p][o], xp[p][3], wB.y);
            }
        }
    }

    // all-reduce partial sums across the 4 lanes of each pixel group
    #pragma unroll
    for (int p = 0; p < PPT; p++) {
        #pragma unroll
        for (int o = 0; o < COUT; o++) {
            u64 t = __shfl_xor_sync(0xffffffffu, acc[p][o], 1);
            add2(acc[p][o], t);
            t = __shfl_xor_sync(0xffffffffu, acc[p][o], 2);
            add2(acc[p][o], t);
        }
    }

    // lane q stores output channels [4q, 4q+4) for its 4 pixels, both batches
    const float4 b4 = *(const float4*)(bias + q * 4);
    #pragma unroll
    for (int p = 0; p < PPT; p++) {
        const int n = wb + p * 8 + g;
        float lo0, hi0, lo1, hi1, lo2, hi2, lo3, hi3;
        unpack2(acc[p][q * 4 + 0], lo0, hi0);
        unpack2(acc[p][q * 4 + 1], lo1, hi1);
        unpack2(acc[p][q * 4 + 2], lo2, hi2);
        unpack2(acc[p][q * 4 + 3], lo3, hi3);
        float4 y0 = make_float4(lo0 + b4.x, lo1 + b4.y, lo2 + b4.z, lo3 + b4.w);
        float4 y1 = make_float4(hi0 + b4.x, hi1 + b4.y, hi2 + b4.z, hi3 + b4.w);
        *(float4*)(y + (size_t)n * COUT + q * 4) = y0;
        *(float4*)(y + (size_t)NPIX * COUT + (size_t)n * COUT + q * 4) = y1;
    }
}

extern "C" void kernel_launch(void* const* d_in, const int* in_sizes, int n_in,
                              void* d_out, int out_size) {
    const float* x    = (const float*)d_in[0];
    const int*   nb   = (const int*)d_in[1];
    const float* w    = (const float*)d_in[2];
    const float* bias = (const float*)d_in[3];
    float*       y    = (float*)d_out;

    // 128 threads = 4 warps = 128 pixels per block
    const int blocks = NPIX / (TPB / 32 * 32);   // 6144
    healpix_conv_kernel<<<blocks, TPB>>>(x, nb, w, bias, y);
}

// round 9
// speedup vs baseline: 1.4346x; 1.4346x over previous
#include <cuda_runtime.h>

#define NPIX 786432
#define KER 9
#define CIN 16
#define COUT 16
#define TPB 128
#define PPT 2          // pixels per thread

typedef unsigned long long u64;

__device__ __forceinline__ u64 pack2(float lo, float hi) {
    u64 r; asm("mov.b64 %0, {%1, %2};" : "=l"(r) : "f"(lo), "f"(hi)); return r;
}
__device__ __forceinline__ void unpack2(u64 v, float& lo, float& hi) {
    asm("mov.b64 {%0, %1}, %2;" : "=f"(lo), "=f"(hi) : "l"(v));
}
__device__ __forceinline__ void fma2(u64& d, u64 a, u64 b) {
    asm("fma.rn.f32x2 %0, %1, %2, %0;" : "+l"(d) : "l"(a), "l"(b));
}
__device__ __forceinline__ void add2(u64& d, u64 a) {
    asm("add.rn.f32x2 %0, %0, %1;" : "+l"(d) : "l"(a));
}

__global__ __launch_bounds__(TPB, 4) void healpix_conv_kernel(
    const float* __restrict__ x,      // (2, NPIX, CIN)
    const int*   __restrict__ nb,     // (NPIX, KER)
    const float* __restrict__ w,      // (COUT, KER, CIN)
    const float* __restrict__ bias,   // (COUT,)
    float*       __restrict__ y)      // (2, NPIX, COUT)
{
    // w duplicated into (w,w) f32x2 pairs, layout [k][o][c]: the 4 lanes of a
    // pixel-group read contiguous c -> conflict-free LDS.128 multi-broadcast.
    __shared__ u64 wdup[KER * COUT * CIN];

    const int tid = threadIdx.x;
    for (int i = tid; i < KER * COUT * CIN; i += TPB) {
        const int c = i & 15;
        const int o = (i >> 4) & 15;
        const int k = i >> 8;
        const float wv = w[(o * KER + k) * CIN + c];
        wdup[i] = pack2(wv, wv);
    }
    __syncthreads();

    const int lane = tid & 31;
    const int warp = tid >> 5;
    const int q = lane & 3;        // channel-quarter owned by this lane
    const int g = lane >> 2;       // pixel group (0..7)
    const int wb = (blockIdx.x * (TPB / 32) + warp) * (PPT * 8);  // 16 px / warp

    u64 acc[PPT][COUT];
    #pragma unroll
    for (int p = 0; p < PPT; p++)
        #pragma unroll
        for (int o = 0; o < COUT; o++) acc[p][o] = 0ULL;

    // quarter-row base pointers for each batch
    const float* xq0 = x + q * 4;
    const float* xq1 = x + (size_t)NPIX * CIN + q * 4;

    const int* nb0 = nb + (size_t)(wb + g) * KER;
    const int* nb1 = nb + (size_t)(wb + 8 + g) * KER;

    // software pipeline depth 1 on the neighbour indices
    int idv[PPT];
    idv[0] = nb0[0];
    idv[1] = nb1[0];

    #pragma unroll 1
    for (int k = 0; k < KER; k++) {
        u64 xp[PPT][4];
        #pragma unroll
        for (int p = 0; p < PPT; p++) {
            const int id = idv[p];
            const int safe = (id < NPIX) ? id : 0;
            const float4 a = *(const float4*)(xq0 + (size_t)safe * CIN);
            const float4 b = *(const float4*)(xq1 + (size_t)safe * CIN);
            const bool valid = (id < NPIX);
            xp[p][0] = valid ? pack2(a.x, b.x) : 0ULL;
            xp[p][1] = valid ? pack2(a.y, b.y) : 0ULL;
            xp[p][2] = valid ? pack2(a.z, b.z) : 0ULL;
            xp[p][3] = valid ? pack2(a.w, b.w) : 0ULL;
        }

        if (k + 1 < KER) {
            idv[0] = nb0[k + 1];
            idv[1] = nb1[k + 1];
        }

        const u64* wk = wdup + k * COUT * CIN + q * 4;
        #pragma unroll
        for (int o = 0; o < COUT; o++) {
            const ulonglong2 wA = *(const ulonglong2*)(wk + o * CIN);
            const ulonglong2 wB = *(const ulonglong2*)(wk + o * CIN + 2);
            #pragma unroll
            for (int p = 0; p < PPT; p++) {
                fma2(acc[p][o], xp[p][0], wA.x);
                fma2(acc[p][o], xp[p][1], wA.y);
                fma2(acc[p][o], xp[p][2], wB.x);
                fma2(acc[p][o], xp[p][3], wB.y);
            }
        }
    }

    // all-reduce partial sums across the 4 lanes of each pixel group
    #pragma unroll
    for (int p = 0; p < PPT; p++) {
        #pragma unroll
        for (int o = 0; o < COUT; o++) {
            u64 t = __shfl_xor_sync(0xffffffffu, acc[p][o], 1);
            add2(acc[p][o], t);
            t = __shfl_xor_sync(0xffffffffu, acc[p][o], 2);
            add2(acc[p][o], t);
        }
    }

    // lane q stores output channels [4q, 4q+4) for its pixels, both batches
    const float4 b4 = *(const float4*)(bias + q * 4);
    #pragma unroll
    for (int p = 0; p < PPT; p++) {
        const int n = wb + p * 8 + g;
        float lo0, hi0, lo1, hi1, lo2, hi2, lo3, hi3;
        unpack2(acc[p][q * 4 + 0], lo0, hi0);
        unpack2(acc[p][q * 4 + 1], lo1, hi1);
        unpack2(acc[p][q * 4 + 2], lo2, hi2);
        unpack2(acc[p][q * 4 + 3], lo3, hi3);
        float4 y0 = make_float4(lo0 + b4.x, lo1 + b4.y, lo2 + b4.z, lo3 + b4.w);
        float4 y1 = make_float4(hi0 + b4.x, hi1 + b4.y, hi2 + b4.z, hi3 + b4.w);
        *(float4*)(y + (size_t)n * COUT + q * 4) = y0;
        *(float4*)(y + (size_t)NPIX * COUT + (size_t)n * COUT + q * 4) = y1;
    }
}

extern "C" void kernel_launch(void* const* d_in, const int* in_sizes, int n_in,
                              void* d_out, int out_size) {
    const float* x    = (const float*)d_in[0];
    const int*   nb   = (const int*)d_in[1];
    const float* w    = (const float*)d_in[2];
    const float* bias = (const float*)d_in[3];
    float*       y    = (float*)d_out;

    // 128 threads = 4 warps = 64 pixels per block
    const int blocks = NPIX / (TPB / 32 * PPT * 8);   // 12288
    healpix_conv_kernel<<<blocks, TPB>>>(x, nb, w, bias, y);
}